// round 1
// baseline (speedup 1.0000x reference)
#include <cuda_runtime.h>
#include <cstdio>

#define D       32
#define KE      96
#define NREL    16
#define NBASE   4
#define TILE_E  64
#define EDGE_BLOCK 128
#define MAX_NODES 50176

// SMEM layout (floats):
//  sRel : [0, 16384)          rel_w[16][32][32]
//  sA   : [16384, 19456)      A_w[96][32]
//  sAb  : [19456, 19488)
//  sBw  : [19488, 19520)
//  sE   : [19520, 25664)      E^T[96][64]
//  sDst : [25664, 25728)  (int)
//  sTyp : [25728, 25792)  (int)
#define SM_FLOATS 25792
#define SMEM_BYTES (SM_FLOATS * 4)

__device__ float gRelW[NREL * D * D];
__device__ float gAgg[MAX_NODES * D];

// ---------------------------------------------------------------------------
// K0: rel_w[t][k][o] = sum_b w_comp[t][b] * weight[b][k][o]
// ---------------------------------------------------------------------------
__global__ void k0_relw(const float* __restrict__ wcomp, const float* __restrict__ weight) {
    int i = blockIdx.x * blockDim.x + threadIdx.x;
    if (i >= NREL * D * D) return;
    int t = i >> 10;          // /1024
    int j = i & 1023;
    float acc = 0.f;
#pragma unroll
    for (int b = 0; b < NBASE; b++)
        acc = fmaf(wcomp[t * NBASE + b], weight[b * D * D + j], acc);
    gRelW[i] = acc;
}

// ---------------------------------------------------------------------------
// K1: init_fea = concat(feat, embed[idx]) @ transform ; also zero gAgg.
// One warp per node, lane = output column.
// ---------------------------------------------------------------------------
__global__ void k1_init(const float* __restrict__ feat,
                        const float* __restrict__ embed,
                        const float* __restrict__ transform,
                        const int* __restrict__ idx,
                        float* __restrict__ out, int n) {
    __shared__ float sT[64 * D];
    for (int i = threadIdx.x; i < 64 * D; i += blockDim.x) sT[i] = transform[i];
    __syncthreads();
    int warp = (blockIdx.x * blockDim.x + threadIdx.x) >> 5;
    int lane = threadIdx.x & 31;
    if (warp >= n) return;
    float f  = feat[(size_t)warp * D + lane];
    float em = embed[(size_t)idx[warp] * D + lane];
    float acc = 0.f;
#pragma unroll
    for (int k = 0; k < 32; k++)
        acc = fmaf(__shfl_sync(0xffffffffu, f, k), sT[k * D + lane], acc);
#pragma unroll
    for (int k = 0; k < 32; k++)
        acc = fmaf(__shfl_sync(0xffffffffu, em, k), sT[(32 + k) * D + lane], acc);
    out[(size_t)warp * 64 + lane] = acc;   // repr[:,0,:]
    gAgg[warp * D + lane] = 0.f;
}

// ---------------------------------------------------------------------------
// K2: edge kernel. 64-edge tiles, register-blocked GEMMs, vector-red scatter.
// init_fea is read from out (stride-64 rows, first 32 floats).
// ---------------------------------------------------------------------------
__global__ __launch_bounds__(EDGE_BLOCK)
void k2_edges(const float* __restrict__ outInit,
              const float* __restrict__ A_w, const float* __restrict__ A_b,
              const float* __restrict__ B_w, const float* __restrict__ B_b,
              const float* __restrict__ attn_emb,
              const int* __restrict__ esrc, const int* __restrict__ edst,
              const int* __restrict__ etyp, int nE) {
    extern __shared__ float sm[];
    float* sRel = sm;
    float* sA   = sm + 16384;
    float* sAb  = sm + 19456;
    float* sBw  = sm + 19488;
    float* sE   = sm + 19520;
    int*   sDst = (int*)(sm + 25664);
    int*   sTyp = (int*)(sm + 25728);

    for (int i = threadIdx.x; i < NREL * D * D; i += blockDim.x) sRel[i] = gRelW[i];
    for (int i = threadIdx.x; i < KE * D; i += blockDim.x) sA[i] = A_w[i];
    if (threadIdx.x < 32) {
        sAb[threadIdx.x] = A_b[threadIdx.x];
        sBw[threadIdx.x] = B_w[threadIdx.x];
    }
    float Bb = B_b[0];
    __syncthreads();

    int tid  = threadIdx.x;
    int lane = tid & 31;
    int w    = tid >> 5;          // warp 0..3
    int og   = lane & 7;          // output group: cols og*4..og*4+3
    int eg   = lane >> 3;         // edge group within warp
    int o0   = og * 4;
    int e0w  = w * 16 + eg * 4;   // first of 4 edges this lane owns

    int nTiles = (nE + TILE_E - 1) / TILE_E;
    for (int tile = blockIdx.x; tile < nTiles; tile += gridDim.x) {
        int t0 = tile * TILE_E;

        // ---- staging: 2 threads per edge fill E^T[96][64] ----
        {
            int e  = tid >> 1;
            int p  = tid & 1;
            int ge = t0 + e;
            int src = 0, dst = 0, typ = 0;
            if (ge < nE) { src = esrc[ge]; dst = edst[ge]; typ = etyp[ge]; }
            if (p == 0) { sDst[e] = dst; sTyp[e] = typ; }
            const float4* row = (const float4*)(outInit + (size_t)(p ? dst : src) * 64);
#pragma unroll
            for (int q = 0; q < 8; q++) {
                float4 v = __ldg(row + q);
                int kb = p * 32 + q * 4;
                sE[(kb + 0) * TILE_E + e] = v.x;
                sE[(kb + 1) * TILE_E + e] = v.y;
                sE[(kb + 2) * TILE_E + e] = v.z;
                sE[(kb + 3) * TILE_E + e] = v.w;
            }
            const float* ar = attn_emb + typ * D + p * 16;
#pragma unroll
            for (int q = 0; q < 16; q++)
                sE[(64 + p * 16 + q) * TILE_E + e] = __ldg(ar + q);
        }
        __syncthreads();

        // ---- G1: hidden = relu(E @ A_w + A_b); s = hidden @ B_w ----
        float acc[4][4];
#pragma unroll
        for (int i = 0; i < 4; i++)
#pragma unroll
            for (int j = 0; j < 4; j++) acc[i][j] = 0.f;

#pragma unroll 4
        for (int k = 0; k < KE; k++) {
            float4 a4 = *(const float4*)&sA[k * D + o0];
            float4 e4 = *(const float4*)&sE[k * TILE_E + e0w];
            float ev[4] = {e4.x, e4.y, e4.z, e4.w};
            float aw[4] = {a4.x, a4.y, a4.z, a4.w};
#pragma unroll
            for (int i = 0; i < 4; i++)
#pragma unroll
                for (int j = 0; j < 4; j++)
                    acc[i][j] = fmaf(ev[i], aw[j], acc[i][j]);
        }

        float4 ab = *(const float4*)&sAb[o0];
        float4 bw = *(const float4*)&sBw[o0];
        float s[4];
#pragma unroll
        for (int i = 0; i < 4; i++) {
            float h0 = fmaxf(acc[i][0] + ab.x, 0.f);
            float h1 = fmaxf(acc[i][1] + ab.y, 0.f);
            float h2 = fmaxf(acc[i][2] + ab.z, 0.f);
            float h3 = fmaxf(acc[i][3] + ab.w, 0.f);
            s[i] = h0 * bw.x + h1 * bw.y + h2 * bw.z + h3 * bw.w;
        }
#pragma unroll
        for (int m = 1; m < 8; m <<= 1) {
#pragma unroll
            for (int i = 0; i < 4; i++)
                s[i] += __shfl_xor_sync(0xffffffffu, s[i], m);
        }
        float av[4];
#pragma unroll
        for (int i = 0; i < 4; i++)
            av[i] = 1.f / (1.f + __expf(-(s[i] + Bb)));

        // ---- G2: msg = x @ rel_w[type] ----
        float m2[4][4];
#pragma unroll
        for (int i = 0; i < 4; i++)
#pragma unroll
            for (int j = 0; j < 4; j++) m2[i][j] = 0.f;

        int ty[4];
#pragma unroll
        for (int i = 0; i < 4; i++) ty[i] = sTyp[e0w + i];

#pragma unroll 2
        for (int k = 0; k < D; k++) {
            float4 x4 = *(const float4*)&sE[k * TILE_E + e0w];
            float xv[4] = {x4.x, x4.y, x4.z, x4.w};
#pragma unroll
            for (int i = 0; i < 4; i++) {
                float4 w4 = *(const float4*)&sRel[ty[i] * (D * D) + k * D + o0];
                m2[i][0] = fmaf(xv[i], w4.x, m2[i][0]);
                m2[i][1] = fmaf(xv[i], w4.y, m2[i][1]);
                m2[i][2] = fmaf(xv[i], w4.z, m2[i][2]);
                m2[i][3] = fmaf(xv[i], w4.w, m2[i][3]);
            }
        }

        // ---- scatter: agg[dst] += a * msg (16B vector red) ----
#pragma unroll
        for (int i = 0; i < 4; i++) {
            int ge = t0 + e0w + i;
            if (ge < nE) {
                float aa = av[i];
                float* p = &gAgg[(size_t)sDst[e0w + i] * D + o0];
                float v0 = aa * m2[i][0], v1 = aa * m2[i][1];
                float v2 = aa * m2[i][2], v3 = aa * m2[i][3];
                asm volatile("red.global.add.v4.f32 [%0], {%1,%2,%3,%4};"
                             :: "l"(p), "f"(v0), "f"(v1), "f"(v2), "f"(v3)
                             : "memory");
            }
        }
        __syncthreads();
    }
}

// ---------------------------------------------------------------------------
// K3: h = relu(init_fea @ self_loop_weight + agg) -> repr[:,1,:]
// ---------------------------------------------------------------------------
__global__ void k3_final(const float* __restrict__ Wself, float* __restrict__ out, int n) {
    __shared__ float sW[D * D];
    for (int i = threadIdx.x; i < D * D; i += blockDim.x) sW[i] = Wself[i];
    __syncthreads();
    int warp = (blockIdx.x * blockDim.x + threadIdx.x) >> 5;
    int lane = threadIdx.x & 31;
    if (warp >= n) return;
    float v = out[(size_t)warp * 64 + lane];
    float acc = 0.f;
#pragma unroll
    for (int k = 0; k < 32; k++)
        acc = fmaf(__shfl_sync(0xffffffffu, v, k), sW[k * D + lane], acc);
    float h = fmaxf(acc + gAgg[warp * D + lane], 0.f);
    out[(size_t)warp * 64 + 32 + lane] = h;
}

// ---------------------------------------------------------------------------
extern "C" void kernel_launch(void* const* d_in, const int* in_sizes, int n_in,
                              void* d_out, int out_size) {
    const float* feat      = (const float*)d_in[0];
    const float* embed     = (const float*)d_in[1];
    const float* transform = (const float*)d_in[2];
    const float* weight    = (const float*)d_in[3];
    const float* wcomp     = (const float*)d_in[4];
    const float* wself     = (const float*)d_in[5];
    const float* A_w       = (const float*)d_in[6];
    const float* A_b       = (const float*)d_in[7];
    const float* B_w       = (const float*)d_in[8];
    const float* B_b       = (const float*)d_in[9];
    const float* attn      = (const float*)d_in[10];
    const int*   idx       = (const int*)d_in[11];
    const int*   esrc      = (const int*)d_in[12];
    const int*   edst      = (const int*)d_in[13];
    const int*   etyp      = (const int*)d_in[14];

    int n  = in_sizes[0] / D;       // 50000
    int nE = in_sizes[12];          // 800000
    float* out = (float*)d_out;

    cudaFuncSetAttribute(k2_edges, cudaFuncAttributeMaxDynamicSharedMemorySize, SMEM_BYTES);

    k0_relw<<<(NREL * D * D + 255) / 256, 256>>>(wcomp, weight);
    k1_init<<<(n + 7) / 8, 256>>>(feat, embed, transform, idx, out, n);
    k2_edges<<<304, EDGE_BLOCK, SMEM_BYTES>>>(out, A_w, A_b, B_w, B_b, attn,
                                              esrc, edst, etyp, nE);
    k3_final<<<(n + 7) / 8, 256>>>(wself, out, n);
}

// round 2
// speedup vs baseline: 1.0007x; 1.0007x over previous
#include <cuda_runtime.h>
#include <cstdio>

#define D       32
#define KE      96
#define NREL    16
#define NBASE   4
#define TILE_E  64
#define EDGE_BLOCK 128
#define MAX_NODES 50176

// SMEM layout (floats):
//  sRel : [0, 16384)          rel_w[16][32][32]
//  sA   : [16384, 19456)      A_w[96][32]
//  sAb  : [19456, 19488)
//  sBw  : [19488, 19520)
//  sE   : [19520, 25664)      E^T[96][64]
//  sDst : [25664, 25728)  (int)
//  sTyp : [25728, 25792)  (int)
#define SM_FLOATS 25792
#define SMEM_BYTES (SM_FLOATS * 4)

__device__ float gRelW[NREL * D * D];
__device__ float gAgg[MAX_NODES * D];

// ---------------------------------------------------------------------------
// K0: rel_w[t][k][o] = sum_b w_comp[t][b] * weight[b][k][o]
// ---------------------------------------------------------------------------
__global__ void k0_relw(const float* __restrict__ wcomp, const float* __restrict__ weight) {
    int i = blockIdx.x * blockDim.x + threadIdx.x;
    if (i >= NREL * D * D) return;
    int t = i >> 10;          // /1024
    int j = i & 1023;
    float acc = 0.f;
#pragma unroll
    for (int b = 0; b < NBASE; b++)
        acc = fmaf(wcomp[t * NBASE + b], weight[b * D * D + j], acc);
    gRelW[i] = acc;
}

// ---------------------------------------------------------------------------
// K1: init_fea = concat(feat, embed[idx]) @ transform ; also zero gAgg.
// One warp per node, lane = output column.
// ---------------------------------------------------------------------------
__global__ void k1_init(const float* __restrict__ feat,
                        const float* __restrict__ embed,
                        const float* __restrict__ transform,
                        const int* __restrict__ idx,
                        float* __restrict__ out, int n) {
    __shared__ float sT[64 * D];
    for (int i = threadIdx.x; i < 64 * D; i += blockDim.x) sT[i] = transform[i];
    __syncthreads();
    int warp = (blockIdx.x * blockDim.x + threadIdx.x) >> 5;
    int lane = threadIdx.x & 31;
    if (warp >= n) return;
    float f  = feat[(size_t)warp * D + lane];
    float em = embed[(size_t)idx[warp] * D + lane];
    float acc = 0.f;
#pragma unroll
    for (int k = 0; k < 32; k++)
        acc = fmaf(__shfl_sync(0xffffffffu, f, k), sT[k * D + lane], acc);
#pragma unroll
    for (int k = 0; k < 32; k++)
        acc = fmaf(__shfl_sync(0xffffffffu, em, k), sT[(32 + k) * D + lane], acc);
    out[(size_t)warp * 64 + lane] = acc;   // repr[:,0,:]
    gAgg[warp * D + lane] = 0.f;
}

// ---------------------------------------------------------------------------
// K2: edge kernel. 64-edge tiles, register-blocked GEMMs, vector-red scatter.
// init_fea is read from out (stride-64 rows, first 32 floats).
// ---------------------------------------------------------------------------
__global__ __launch_bounds__(EDGE_BLOCK)
void k2_edges(const float* __restrict__ outInit,
              const float* __restrict__ A_w, const float* __restrict__ A_b,
              const float* __restrict__ B_w, const float* __restrict__ B_b,
              const float* __restrict__ attn_emb,
              const int* __restrict__ esrc, const int* __restrict__ edst,
              const int* __restrict__ etyp, int nE) {
    extern __shared__ float sm[];
    float* sRel = sm;
    float* sA   = sm + 16384;
    float* sAb  = sm + 19456;
    float* sBw  = sm + 19488;
    float* sE   = sm + 19520;
    int*   sDst = (int*)(sm + 25664);
    int*   sTyp = (int*)(sm + 25728);

    for (int i = threadIdx.x; i < NREL * D * D; i += blockDim.x) sRel[i] = gRelW[i];
    for (int i = threadIdx.x; i < KE * D; i += blockDim.x) sA[i] = A_w[i];
    if (threadIdx.x < 32) {
        sAb[threadIdx.x] = A_b[threadIdx.x];
        sBw[threadIdx.x] = B_w[threadIdx.x];
    }
    float Bb = B_b[0];
    __syncthreads();

    int tid  = threadIdx.x;
    int lane = tid & 31;
    int w    = tid >> 5;          // warp 0..3
    int og   = lane & 7;          // output group: cols og*4..og*4+3
    int eg   = lane >> 3;         // edge group within warp
    int o0   = og * 4;
    int e0w  = w * 16 + eg * 4;   // first of 4 edges this lane owns

    int nTiles = (nE + TILE_E - 1) / TILE_E;
    for (int tile = blockIdx.x; tile < nTiles; tile += gridDim.x) {
        int t0 = tile * TILE_E;

        // ---- staging: 2 threads per edge fill E^T[96][64] ----
        {
            int e  = tid >> 1;
            int p  = tid & 1;
            int ge = t0 + e;
            int src = 0, dst = 0, typ = 0;
            if (ge < nE) { src = esrc[ge]; dst = edst[ge]; typ = etyp[ge]; }
            if (p == 0) { sDst[e] = dst; sTyp[e] = typ; }
            const float4* row = (const float4*)(outInit + (size_t)(p ? dst : src) * 64);
#pragma unroll
            for (int q = 0; q < 8; q++) {
                float4 v = __ldg(row + q);
                int kb = p * 32 + q * 4;
                sE[(kb + 0) * TILE_E + e] = v.x;
                sE[(kb + 1) * TILE_E + e] = v.y;
                sE[(kb + 2) * TILE_E + e] = v.z;
                sE[(kb + 3) * TILE_E + e] = v.w;
            }
            const float* ar = attn_emb + typ * D + p * 16;
#pragma unroll
            for (int q = 0; q < 16; q++)
                sE[(64 + p * 16 + q) * TILE_E + e] = __ldg(ar + q);
        }
        __syncthreads();

        // ---- G1: hidden = relu(E @ A_w + A_b); s = hidden @ B_w ----
        float acc[4][4];
#pragma unroll
        for (int i = 0; i < 4; i++)
#pragma unroll
            for (int j = 0; j < 4; j++) acc[i][j] = 0.f;

#pragma unroll 4
        for (int k = 0; k < KE; k++) {
            float4 a4 = *(const float4*)&sA[k * D + o0];
            float4 e4 = *(const float4*)&sE[k * TILE_E + e0w];
            float ev[4] = {e4.x, e4.y, e4.z, e4.w};
            float aw[4] = {a4.x, a4.y, a4.z, a4.w};
#pragma unroll
            for (int i = 0; i < 4; i++)
#pragma unroll
                for (int j = 0; j < 4; j++)
                    acc[i][j] = fmaf(ev[i], aw[j], acc[i][j]);
        }

        float4 ab = *(const float4*)&sAb[o0];
        float4 bw = *(const float4*)&sBw[o0];
        float s[4];
#pragma unroll
        for (int i = 0; i < 4; i++) {
            float h0 = fmaxf(acc[i][0] + ab.x, 0.f);
            float h1 = fmaxf(acc[i][1] + ab.y, 0.f);
            float h2 = fmaxf(acc[i][2] + ab.z, 0.f);
            float h3 = fmaxf(acc[i][3] + ab.w, 0.f);
            s[i] = h0 * bw.x + h1 * bw.y + h2 * bw.z + h3 * bw.w;
        }
#pragma unroll
        for (int m = 1; m < 8; m <<= 1) {
#pragma unroll
            for (int i = 0; i < 4; i++)
                s[i] += __shfl_xor_sync(0xffffffffu, s[i], m);
        }
        float av[4];
#pragma unroll
        for (int i = 0; i < 4; i++)
            av[i] = 1.f / (1.f + __expf(-(s[i] + Bb)));

        // ---- G2: msg = x @ rel_w[type] ----
        float m2[4][4];
#pragma unroll
        for (int i = 0; i < 4; i++)
#pragma unroll
            for (int j = 0; j < 4; j++) m2[i][j] = 0.f;

        int ty[4];
#pragma unroll
        for (int i = 0; i < 4; i++) ty[i] = sTyp[e0w + i];

#pragma unroll 2
        for (int k = 0; k < D; k++) {
            float4 x4 = *(const float4*)&sE[k * TILE_E + e0w];
            float xv[4] = {x4.x, x4.y, x4.z, x4.w};
#pragma unroll
            for (int i = 0; i < 4; i++) {
                float4 w4 = *(const float4*)&sRel[ty[i] * (D * D) + k * D + o0];
                m2[i][0] = fmaf(xv[i], w4.x, m2[i][0]);
                m2[i][1] = fmaf(xv[i], w4.y, m2[i][1]);
                m2[i][2] = fmaf(xv[i], w4.z, m2[i][2]);
                m2[i][3] = fmaf(xv[i], w4.w, m2[i][3]);
            }
        }

        // ---- scatter: agg[dst] += a * msg (16B vector red) ----
#pragma unroll
        for (int i = 0; i < 4; i++) {
            int ge = t0 + e0w + i;
            if (ge < nE) {
                float aa = av[i];
                float* p = &gAgg[(size_t)sDst[e0w + i] * D + o0];
                float v0 = aa * m2[i][0], v1 = aa * m2[i][1];
                float v2 = aa * m2[i][2], v3 = aa * m2[i][3];
                asm volatile("red.global.add.v4.f32 [%0], {%1,%2,%3,%4};"
                             :: "l"(p), "f"(v0), "f"(v1), "f"(v2), "f"(v3)
                             : "memory");
            }
        }
        __syncthreads();
    }
}

// ---------------------------------------------------------------------------
// K3: h = relu(init_fea @ self_loop_weight + agg) -> repr[:,1,:]
// ---------------------------------------------------------------------------
__global__ void k3_final(const float* __restrict__ Wself, float* __restrict__ out, int n) {
    __shared__ float sW[D * D];
    for (int i = threadIdx.x; i < D * D; i += blockDim.x) sW[i] = Wself[i];
    __syncthreads();
    int warp = (blockIdx.x * blockDim.x + threadIdx.x) >> 5;
    int lane = threadIdx.x & 31;
    if (warp >= n) return;
    float v = out[(size_t)warp * 64 + lane];
    float acc = 0.f;
#pragma unroll
    for (int k = 0; k < 32; k++)
        acc = fmaf(__shfl_sync(0xffffffffu, v, k), sW[k * D + lane], acc);
    float h = fmaxf(acc + gAgg[warp * D + lane], 0.f);
    out[(size_t)warp * 64 + 32 + lane] = h;
}

// ---------------------------------------------------------------------------
extern "C" void kernel_launch(void* const* d_in, const int* in_sizes, int n_in,
                              void* d_out, int out_size) {
    const float* feat      = (const float*)d_in[0];
    const float* embed     = (const float*)d_in[1];
    const float* transform = (const float*)d_in[2];
    const float* weight    = (const float*)d_in[3];
    const float* wcomp     = (const float*)d_in[4];
    const float* wself     = (const float*)d_in[5];
    const float* A_w       = (const float*)d_in[6];
    const float* A_b       = (const float*)d_in[7];
    const float* B_w       = (const float*)d_in[8];
    const float* B_b       = (const float*)d_in[9];
    const float* attn      = (const float*)d_in[10];
    const int*   idx       = (const int*)d_in[11];
    const int*   esrc      = (const int*)d_in[12];
    const int*   edst      = (const int*)d_in[13];
    const int*   etyp      = (const int*)d_in[14];

    int n  = in_sizes[0] / D;       // 50000
    int nE = in_sizes[12];          // 800000
    float* out = (float*)d_out;

    cudaFuncSetAttribute(k2_edges, cudaFuncAttributeMaxDynamicSharedMemorySize, SMEM_BYTES);

    k0_relw<<<(NREL * D * D + 255) / 256, 256>>>(wcomp, weight);
    k1_init<<<(n + 7) / 8, 256>>>(feat, embed, transform, idx, out, n);
    k2_edges<<<304, EDGE_BLOCK, SMEM_BYTES>>>(out, A_w, A_b, B_w, B_b, attn,
                                              esrc, edst, etyp, nE);
    k3_final<<<(n + 7) / 8, 256>>>(wself, out, n);
}

// round 3
// speedup vs baseline: 2.7440x; 2.7422x over previous
#include <cuda_runtime.h>

#define D        32
#define NREL     16
#define NBASE    4
#define MAX_NODES 50176

// Per-node precomputed source data: {px[32], z0[32], z1[32], z2[32], z3[32]} = 160 floats
__device__ float gS[MAX_NODES * 160];
__device__ float gPy[MAX_NODES * D];
__device__ float gAgg[MAX_NODES * D];   // initialized with curr = init_fea @ self_loop
__device__ float gPr[NREL * D];         // attn_emb @ Ar + A_b

// ---------------------------------------------------------------------------
// K0: pr[t][o] = sum_k attn_emb[t][k] * A_w[64+k][o] + A_b[o]
// ---------------------------------------------------------------------------
__global__ void k0_pr(const float* __restrict__ attn, const float* __restrict__ A_w,
                      const float* __restrict__ A_b) {
    int tid = threadIdx.x;           // 512 threads
    int t = tid >> 5, o = tid & 31;
    float acc = A_b[o];
#pragma unroll
    for (int k = 0; k < D; k++)
        acc = fmaf(attn[t * D + k], A_w[(64 + k) * D + o], acc);
    gPr[tid] = acc;
}

// ---------------------------------------------------------------------------
// K1: per-node precompute. One warp per node, lane = column.
//   init_fea = concat(feat, embed[idx]) @ transform     -> out[:,0,:]
//   px = init@Ax, py = init@Ay, z_b = init@W_b, curr = init@Wself -> gAgg
// ---------------------------------------------------------------------------
__global__ void k1_init(const float* __restrict__ feat,
                        const float* __restrict__ embed,
                        const float* __restrict__ transform,
                        const float* __restrict__ A_w,     // rows 0..63 = Ax, Ay
                        const float* __restrict__ weight,  // [4][32][32]
                        const float* __restrict__ wself,
                        const int* __restrict__ idx,
                        float* __restrict__ out, int n) {
    __shared__ float sT[64 * D];       // transform
    __shared__ float sM[7 * D * D];    // Ax, Ay, W0..W3, Wself
    for (int i = threadIdx.x; i < 64 * D; i += blockDim.x) sT[i] = transform[i];
    for (int i = threadIdx.x; i < 2 * D * D; i += blockDim.x) sM[i] = A_w[i];
    for (int i = threadIdx.x; i < 4 * D * D; i += blockDim.x) sM[2048 + i] = weight[i];
    for (int i = threadIdx.x; i < D * D; i += blockDim.x) sM[6144 + i] = wself[i];
    __syncthreads();

    int warp = (blockIdx.x * blockDim.x + threadIdx.x) >> 5;
    int lane = threadIdx.x & 31;
    if (warp >= n) return;

    float f  = feat[(size_t)warp * D + lane];
    float em = embed[(size_t)idx[warp] * D + lane];
    float v = 0.f;
#pragma unroll
    for (int k = 0; k < 32; k++)
        v = fmaf(__shfl_sync(0xffffffffu, f, k), sT[k * D + lane], v);
#pragma unroll
    for (int k = 0; k < 32; k++)
        v = fmaf(__shfl_sync(0xffffffffu, em, k), sT[(32 + k) * D + lane], v);
    out[(size_t)warp * 64 + lane] = v;   // repr[:,0,:]

    float a0 = 0.f, a1 = 0.f, a2 = 0.f, a3 = 0.f, a4 = 0.f, a5 = 0.f, a6 = 0.f;
#pragma unroll
    for (int k = 0; k < 32; k++) {
        float bc = __shfl_sync(0xffffffffu, v, k);
        int base = k * D + lane;
        a0 = fmaf(bc, sM[base], a0);            // px
        a1 = fmaf(bc, sM[1024 + base], a1);     // py
        a2 = fmaf(bc, sM[2048 + base], a2);     // z0
        a3 = fmaf(bc, sM[3072 + base], a3);     // z1
        a4 = fmaf(bc, sM[4096 + base], a4);     // z2
        a5 = fmaf(bc, sM[5120 + base], a5);     // z3
        a6 = fmaf(bc, sM[6144 + base], a6);     // curr
    }
    size_t s0 = (size_t)warp * 160;
    gS[s0 + lane]        = a0;
    gS[s0 + 32 + lane]   = a2;
    gS[s0 + 64 + lane]   = a3;
    gS[s0 + 96 + lane]   = a4;
    gS[s0 + 128 + lane]  = a5;
    gPy[(size_t)warp * D + lane]  = a1;
    gAgg[(size_t)warp * D + lane] = a6;
}

// ---------------------------------------------------------------------------
// K2: edge kernel. 4 edges per warp, 8 lanes/edge, each lane one float4 chunk.
//   h = relu(px + py + pr); s = h . B_w (reduce over 8 lanes); a = sigmoid(s+Bb)
//   msg = a * (wc0*z0 + wc1*z1 + wc2*z2 + wc3*z3); red.add.v4 -> gAgg[dst]
// ---------------------------------------------------------------------------
__global__ __launch_bounds__(256)
void k2_edges(const float* __restrict__ B_w, const float* __restrict__ B_b,
              const float* __restrict__ wcomp,
              const int* __restrict__ esrc, const int* __restrict__ edst,
              const int* __restrict__ etyp, int nE) {
    __shared__ float sPr[NREL * D];
    __shared__ float sWc[NREL * NBASE];
    for (int i = threadIdx.x; i < NREL * D; i += blockDim.x) sPr[i] = gPr[i];
    for (int i = threadIdx.x; i < NREL * NBASE; i += blockDim.x) sWc[i] = wcomp[i];
    __syncthreads();

    int lane = threadIdx.x & 31;
    int c    = lane & 7;        // float4 chunk 0..7
    int ei   = lane >> 3;       // edge within quad 0..3
    float Bb = __ldg(B_b);
    float4 Bw4 = __ldg((const float4*)B_w + c);

    int gwarp = (blockIdx.x * blockDim.x + threadIdx.x) >> 5;
    int nWarps = (gridDim.x * blockDim.x) >> 5;
    int nQ = (nE + 3) >> 2;

    const float4* Sv  = (const float4*)gS;
    const float4* Pyv = (const float4*)gPy;
    const float4* Prv = (const float4*)sPr;
    const float4* Wcv = (const float4*)sWc;

    for (int q = gwarp; q < nQ; q += nWarps) {
        int ge = q * 4 + ei;
        bool valid = ge < nE;
        int gc = valid ? ge : (nE - 1);
        int src = __ldg(esrc + gc);
        int dst = __ldg(edst + gc);
        int typ = __ldg(etyp + gc);

        size_t srow = (size_t)src * 40;
        float4 px4 = __ldg(Sv + srow + c);
        float4 z0  = __ldg(Sv + srow + 8 + c);
        float4 z1  = __ldg(Sv + srow + 16 + c);
        float4 z2  = __ldg(Sv + srow + 24 + c);
        float4 z3  = __ldg(Sv + srow + 32 + c);
        float4 py4 = __ldg(Pyv + (size_t)dst * 8 + c);
        float4 pr4 = Prv[typ * 8 + c];

        float hx = fmaxf(px4.x + py4.x + pr4.x, 0.f);
        float hy = fmaxf(px4.y + py4.y + pr4.y, 0.f);
        float hz = fmaxf(px4.z + py4.z + pr4.z, 0.f);
        float hw = fmaxf(px4.w + py4.w + pr4.w, 0.f);
        float s = hx * Bw4.x + hy * Bw4.y + hz * Bw4.z + hw * Bw4.w;
        s += __shfl_xor_sync(0xffffffffu, s, 1);
        s += __shfl_xor_sync(0xffffffffu, s, 2);
        s += __shfl_xor_sync(0xffffffffu, s, 4);
        float a = 1.f / (1.f + __expf(-(s + Bb)));

        float4 wc = Wcv[typ];
        float mx = wc.x * z0.x; mx = fmaf(wc.y, z1.x, mx); mx = fmaf(wc.z, z2.x, mx); mx = fmaf(wc.w, z3.x, mx);
        float my = wc.x * z0.y; my = fmaf(wc.y, z1.y, my); my = fmaf(wc.z, z2.y, my); my = fmaf(wc.w, z3.y, my);
        float mz = wc.x * z0.z; mz = fmaf(wc.y, z1.z, mz); mz = fmaf(wc.z, z2.z, mz); mz = fmaf(wc.w, z3.z, mz);
        float mw = wc.x * z0.w; mw = fmaf(wc.y, z1.w, mw); mw = fmaf(wc.z, z2.w, mw); mw = fmaf(wc.w, z3.w, mw);
        mx *= a; my *= a; mz *= a; mw *= a;

        if (valid) {
            float* p = &gAgg[(size_t)dst * D + c * 4];
            asm volatile("red.global.add.v4.f32 [%0], {%1,%2,%3,%4};"
                         :: "l"(p), "f"(mx), "f"(my), "f"(mz), "f"(mw)
                         : "memory");
        }
    }
}

// ---------------------------------------------------------------------------
// K3: repr[:,1,:] = relu(gAgg)
// ---------------------------------------------------------------------------
__global__ void k3_final(float* __restrict__ out, int n) {
    int i = blockIdx.x * blockDim.x + threadIdx.x;   // float4 index
    int total = n * 8;                                // n*32/4
    if (i >= total) return;
    int v = i >> 3, c = i & 7;
    float4 g = ((const float4*)gAgg)[i];
    float4 r;
    r.x = fmaxf(g.x, 0.f); r.y = fmaxf(g.y, 0.f);
    r.z = fmaxf(g.z, 0.f); r.w = fmaxf(g.w, 0.f);
    ((float4*)out)[(size_t)v * 16 + 8 + c] = r;
}

// ---------------------------------------------------------------------------
extern "C" void kernel_launch(void* const* d_in, const int* in_sizes, int n_in,
                              void* d_out, int out_size) {
    const float* feat      = (const float*)d_in[0];
    const float* embed     = (const float*)d_in[1];
    const float* transform = (const float*)d_in[2];
    const float* weight    = (const float*)d_in[3];
    const float* wcomp     = (const float*)d_in[4];
    const float* wself     = (const float*)d_in[5];
    const float* A_w       = (const float*)d_in[6];
    const float* A_b       = (const float*)d_in[7];
    const float* B_w       = (const float*)d_in[8];
    const float* B_b       = (const float*)d_in[9];
    const float* attn      = (const float*)d_in[10];
    const int*   idx       = (const int*)d_in[11];
    const int*   esrc      = (const int*)d_in[12];
    const int*   edst      = (const int*)d_in[13];
    const int*   etyp      = (const int*)d_in[14];

    int n  = in_sizes[0] / D;       // 50000
    int nE = in_sizes[12];          // 800000
    float* out = (float*)d_out;

    k0_pr<<<1, NREL * D>>>(attn, A_w, A_b);
    k1_init<<<(n + 7) / 8, 256>>>(feat, embed, transform, A_w, weight, wself, idx, out, n);
    k2_edges<<<2368, 256>>>(B_w, B_b, wcomp, esrc, edst, etyp, nE);
    k3_final<<<(n * 8 + 255) / 256, 256>>>(out, n);
}

// round 4
// speedup vs baseline: 4.0846x; 1.4885x over previous
#include <cuda_runtime.h>
#include <cuda_fp16.h>

#define D        32
#define NREL     16
#define NBASE    4
#define MAX_NODES 50176
#define NT       128          // nodes per k1 block

__device__ float  gPx[MAX_NODES * D];
__device__ float  gPy[MAX_NODES * D];
__device__ float  gAgg[MAX_NODES * D];          // init: curr = init_fea @ Wself
__device__ __half gSh[MAX_NODES * 128];         // z0..z3 fp16, layout [node][chunk c][b][j]

// k1 SMEM: sT[64*32]=2048 | sW[32*224]=7168 | sF[64*128]=8192 (sI aliases sF)
#define K1_SMEM_FLOATS (2048 + 7168 + 8192)
#define K1_SMEM_BYTES  (K1_SMEM_FLOATS * 4)

// ---------------------------------------------------------------------------
// K1: per-node precompute, tiled GEMM form.
//   GEMM1: init = [feat | embed[idx]] @ transform          (128x64 @ 64x32)
//   GEMM2: init @ [Ax | Ay | W0..W3 | Wself]               (128x32 @ 32x224)
// ---------------------------------------------------------------------------
__global__ __launch_bounds__(256)
void k1_init(const float* __restrict__ feat,
             const float* __restrict__ embed,
             const float* __restrict__ transform,
             const float* __restrict__ A_w,     // [96][32]; rows 0..63 = Ax,Ay
             const float* __restrict__ weight,  // [4][32][32]
             const float* __restrict__ wself,
             const int* __restrict__ idx,
             float* __restrict__ out, int n) {
    extern __shared__ float sm[];
    float* sT = sm;              // [64][32]
    float* sW = sm + 2048;       // [32][224]
    float* sF = sm + 2048 + 7168;// [64][128]
    float* sI = sF;              // [32][128] alias (used after GEMM1)

    int tid = threadIdx.x;
    // --- stage weights ---
    for (int i = tid; i < 2048; i += 256) sT[i] = transform[i];
    for (int i = tid; i < 2048; i += 256) {            // Ax,Ay
        int k = (i >> 5) & 31, part = i >> 10, c = i & 31;
        sW[k * 224 + part * 32 + c] = A_w[i];
    }
    for (int i = tid; i < 4096; i += 256) {            // W0..W3
        int b = i >> 10, k = (i >> 5) & 31, c = i & 31;
        sW[k * 224 + 64 + b * 32 + c] = weight[i];
    }
    for (int i = tid; i < 1024; i += 256) {            // Wself
        sW[(i >> 5) * 224 + 192 + (i & 31)] = wself[i];
    }

    // --- stage node features transposed: sF[k][nl] ---
    int base = blockIdx.x * NT;
    {
        int p  = tid >> 7;        // half of the 32-feature row
        int nl = tid & 127;
        int node = base + nl;
        int nc = node < n ? node : n - 1;
        const float4* fr = (const float4*)feat + (size_t)nc * 8 + p * 4;
        const float4* er = (const float4*)embed + (size_t)__ldg(idx + nc) * 8 + p * 4;
#pragma unroll
        for (int q = 0; q < 4; q++) {
            float4 v = __ldg(fr + q);
            int r = p * 16 + q * 4;
            sF[(r + 0) * NT + nl] = v.x; sF[(r + 1) * NT + nl] = v.y;
            sF[(r + 2) * NT + nl] = v.z; sF[(r + 3) * NT + nl] = v.w;
            float4 w = __ldg(er + q);
            int r2 = 32 + p * 16 + q * 4;
            sF[(r2 + 0) * NT + nl] = w.x; sF[(r2 + 1) * NT + nl] = w.y;
            sF[(r2 + 2) * NT + nl] = w.z; sF[(r2 + 3) * NT + nl] = w.w;
        }
    }
    __syncthreads();

    int w   = tid >> 5;
    int lane = tid & 31;
    int cg  = lane & 7;
    int ngl = lane >> 3;
    int n0  = w * 16 + ngl * 4;     // 4 nodes
    int c0  = cg * 4;               // 4 cols

    // --- GEMM1 ---
    float acc[4][4];
#pragma unroll
    for (int i = 0; i < 4; i++)
#pragma unroll
        for (int j = 0; j < 4; j++) acc[i][j] = 0.f;
#pragma unroll 8
    for (int k = 0; k < 64; k++) {
        float4 tv = *(const float4*)&sT[k * 32 + c0];
        float4 fv = *(const float4*)&sF[k * NT + n0];
        float f[4] = {fv.x, fv.y, fv.z, fv.w};
        float t[4] = {tv.x, tv.y, tv.z, tv.w};
#pragma unroll
        for (int i = 0; i < 4; i++)
#pragma unroll
            for (int j = 0; j < 4; j++)
                acc[i][j] = fmaf(f[i], t[j], acc[i][j]);
    }
    __syncthreads();   // all sF reads done; sI may overwrite

    // epilogue: write init_fea to out[:,0,:] and transposed copy into sI
#pragma unroll
    for (int i = 0; i < 4; i++) {
        int node = base + n0 + i;
        if (node < n) {
            float4 v = make_float4(acc[i][0], acc[i][1], acc[i][2], acc[i][3]);
            *(float4*)&out[(size_t)node * 64 + c0] = v;
        }
#pragma unroll
        for (int j = 0; j < 4; j++)
            sI[(c0 + j) * NT + n0 + i] = acc[i][j];
    }
    __syncthreads();

    // --- GEMM2: 7 projections ---
#pragma unroll
    for (int pj = 0; pj < 7; pj++) {
        float a2[4][4];
#pragma unroll
        for (int i = 0; i < 4; i++)
#pragma unroll
            for (int j = 0; j < 4; j++) a2[i][j] = 0.f;
#pragma unroll 4
        for (int k = 0; k < 32; k++) {
            float4 nv = *(const float4*)&sI[k * NT + n0];
            float4 wv = *(const float4*)&sW[k * 224 + pj * 32 + c0];
            float f[4] = {nv.x, nv.y, nv.z, nv.w};
            float t[4] = {wv.x, wv.y, wv.z, wv.w};
#pragma unroll
            for (int i = 0; i < 4; i++)
#pragma unroll
                for (int j = 0; j < 4; j++)
                    a2[i][j] = fmaf(f[i], t[j], a2[i][j]);
        }
#pragma unroll
        for (int i = 0; i < 4; i++) {
            int node = base + n0 + i;
            if (node >= n) continue;
            float4 v = make_float4(a2[i][0], a2[i][1], a2[i][2], a2[i][3]);
            if (pj == 0) {
                *(float4*)&gPx[(size_t)node * D + c0] = v;
            } else if (pj == 1) {
                *(float4*)&gPy[(size_t)node * D + c0] = v;
            } else if (pj == 6) {
                *(float4*)&gAgg[(size_t)node * D + c0] = v;
            } else {
                int b = pj - 2;
                __half2 h01 = __floats2half2_rn(v.x, v.y);
                __half2 h23 = __floats2half2_rn(v.z, v.w);
                uint2 pk;
                pk.x = *(unsigned*)&h01;
                pk.y = *(unsigned*)&h23;
                *(uint2*)&gSh[(size_t)node * 128 + cg * 16 + b * 4] = pk;
            }
        }
    }
}

// ---------------------------------------------------------------------------
// K2: edge kernel. 4 edges/warp, 8 lanes/edge (lane c = float4 chunk).
//   pr computed in-block (replaces k0).
// ---------------------------------------------------------------------------
__global__ __launch_bounds__(256)
void k2_edges(const float* __restrict__ A_w, const float* __restrict__ A_b,
              const float* __restrict__ B_w, const float* __restrict__ B_b,
              const float* __restrict__ attn, const float* __restrict__ wcomp,
              const int* __restrict__ esrc, const int* __restrict__ edst,
              const int* __restrict__ etyp, int nE) {
    __shared__ float sPr[NREL * D];
    __shared__ float sWc[NREL * NBASE];
    int tid = threadIdx.x;
    for (int i = tid; i < NREL * D; i += 256) {
        int t = i >> 5, o = i & 31;
        float acc = __ldg(A_b + o);
#pragma unroll
        for (int k = 0; k < D; k++)
            acc = fmaf(__ldg(attn + t * D + k), __ldg(A_w + (64 + k) * D + o), acc);
        sPr[i] = acc;
    }
    if (tid < NREL * NBASE) sWc[tid] = wcomp[tid];
    __syncthreads();

    int lane = tid & 31;
    int c    = lane & 7;
    int ei   = lane >> 3;
    float Bb = __ldg(B_b);
    float4 Bw4 = __ldg((const float4*)B_w + c);

    int gwarp = (blockIdx.x * blockDim.x + tid) >> 5;
    int nWarps = (gridDim.x * blockDim.x) >> 5;
    int nQ = (nE + 3) >> 2;

    const float4* Pxv = (const float4*)gPx;
    const float4* Pyv = (const float4*)gPy;
    const uint4*  Zv  = (const uint4*)gSh;
    const float4* Prv = (const float4*)sPr;
    const float4* Wcv = (const float4*)sWc;

    for (int q = gwarp; q < nQ; q += nWarps) {
        int ge = q * 4 + ei;
        bool valid = ge < nE;
        int gc = valid ? ge : (nE - 1);
        int src = __ldg(esrc + gc);
        int dst = __ldg(edst + gc);
        int typ = __ldg(etyp + gc);

        float4 px4 = __ldg(Pxv + (size_t)src * 8 + c);
        float4 py4 = __ldg(Pyv + (size_t)dst * 8 + c);
        uint4 u0 = __ldg(Zv + (size_t)src * 16 + c * 2);       // b0,b1
        uint4 u1 = __ldg(Zv + (size_t)src * 16 + c * 2 + 1);   // b2,b3
        float4 pr4 = Prv[typ * 8 + c];

        float hx = fmaxf(px4.x + py4.x + pr4.x, 0.f);
        float hy = fmaxf(px4.y + py4.y + pr4.y, 0.f);
        float hz = fmaxf(px4.z + py4.z + pr4.z, 0.f);
        float hw = fmaxf(px4.w + py4.w + pr4.w, 0.f);
        float s = hx * Bw4.x + hy * Bw4.y + hz * Bw4.z + hw * Bw4.w;
        s += __shfl_xor_sync(0xffffffffu, s, 1);
        s += __shfl_xor_sync(0xffffffffu, s, 2);
        s += __shfl_xor_sync(0xffffffffu, s, 4);
        float a = 1.f / (1.f + __expf(-(s + Bb)));

        // unpack z (layout within 16 halfs: b*4 + j)
        float2 f00 = __half22float2(*(const __half2*)&u0.x);  // b0 j0,j1
        float2 f01 = __half22float2(*(const __half2*)&u0.y);  // b0 j2,j3
        float2 f10 = __half22float2(*(const __half2*)&u0.z);  // b1 j0,j1
        float2 f11 = __half22float2(*(const __half2*)&u0.w);  // b1 j2,j3
        float2 f20 = __half22float2(*(const __half2*)&u1.x);  // b2 j0,j1
        float2 f21 = __half22float2(*(const __half2*)&u1.y);
        float2 f30 = __half22float2(*(const __half2*)&u1.z);  // b3 j0,j1
        float2 f31 = __half22float2(*(const __half2*)&u1.w);

        float4 wc = Wcv[typ];
        float mx = wc.x * f00.x; mx = fmaf(wc.y, f10.x, mx); mx = fmaf(wc.z, f20.x, mx); mx = fmaf(wc.w, f30.x, mx);
        float my = wc.x * f00.y; my = fmaf(wc.y, f10.y, my); my = fmaf(wc.z, f20.y, my); my = fmaf(wc.w, f30.y, my);
        float mz = wc.x * f01.x; mz = fmaf(wc.y, f11.x, mz); mz = fmaf(wc.z, f21.x, mz); mz = fmaf(wc.w, f31.x, mz);
        float mw = wc.x * f01.y; mw = fmaf(wc.y, f11.y, mw); mw = fmaf(wc.z, f21.y, mw); mw = fmaf(wc.w, f31.y, mw);
        mx *= a; my *= a; mz *= a; mw *= a;

        if (valid) {
            float* p = &gAgg[(size_t)dst * D + c * 4];
            asm volatile("red.global.add.v4.f32 [%0], {%1,%2,%3,%4};"
                         :: "l"(p), "f"(mx), "f"(my), "f"(mz), "f"(mw)
                         : "memory");
        }
    }
}

// ---------------------------------------------------------------------------
// K3: repr[:,1,:] = relu(gAgg)
// ---------------------------------------------------------------------------
__global__ void k3_final(float* __restrict__ out, int n) {
    int i = blockIdx.x * blockDim.x + threadIdx.x;
    int total = n * 8;
    if (i >= total) return;
    int v = i >> 3, cc = i & 7;
    float4 g = ((const float4*)gAgg)[i];
    float4 r;
    r.x = fmaxf(g.x, 0.f); r.y = fmaxf(g.y, 0.f);
    r.z = fmaxf(g.z, 0.f); r.w = fmaxf(g.w, 0.f);
    ((float4*)out)[(size_t)v * 16 + 8 + cc] = r;
}

// ---------------------------------------------------------------------------
extern "C" void kernel_launch(void* const* d_in, const int* in_sizes, int n_in,
                              void* d_out, int out_size) {
    const float* feat      = (const float*)d_in[0];
    const float* embed     = (const float*)d_in[1];
    const float* transform = (const float*)d_in[2];
    const float* weight    = (const float*)d_in[3];
    const float* wcomp     = (const float*)d_in[4];
    const float* wself     = (const float*)d_in[5];
    const float* A_w       = (const float*)d_in[6];
    const float* A_b       = (const float*)d_in[7];
    const float* B_w       = (const float*)d_in[8];
    const float* B_b       = (const float*)d_in[9];
    const float* attn      = (const float*)d_in[10];
    const int*   idx       = (const int*)d_in[11];
    const int*   esrc      = (const int*)d_in[12];
    const int*   edst      = (const int*)d_in[13];
    const int*   etyp      = (const int*)d_in[14];

    int n  = in_sizes[0] / D;       // 50000
    int nE = in_sizes[12];          // 800000
    float* out = (float*)d_out;

    cudaFuncSetAttribute(k1_init, cudaFuncAttributeMaxDynamicSharedMemorySize, K1_SMEM_BYTES);

    k1_init<<<(n + NT - 1) / NT, 256, K1_SMEM_BYTES>>>(feat, embed, transform, A_w,
                                                       weight, wself, idx, out, n);
    k2_edges<<<1184, 256>>>(A_w, A_b, B_w, B_b, attn, wcomp, esrc, edst, etyp, nE);
    k3_final<<<(n * 8 + 255) / 256, 256>>>(out, n);
}

// round 5
// speedup vs baseline: 4.4834x; 1.0976x over previous
#include <cuda_runtime.h>
#include <cuda_fp16.h>

#define D        32
#define NREL     16
#define NBASE    4
#define MAX_NODES 50176
#define NT       128          // nodes per k1 block

__device__ float  gPx[MAX_NODES * D];
__device__ float  gPy[MAX_NODES * D];
__device__ float  gAgg[MAX_NODES * D];          // init: curr = init_fea @ Wself
__device__ __half gSh[MAX_NODES * 128];         // z0..z3 fp16, layout [node][chunk c][b][j]

// k1 SMEM: sT[64*32]=2048 | sW[32*224]=7168 | sF[32*128]=4096 (two passes; sI aliases)
#define K1_SMEM_FLOATS (2048 + 7168 + 4096)
#define K1_SMEM_BYTES  (K1_SMEM_FLOATS * 4)

// ---------------------------------------------------------------------------
// K1: per-node precompute, tiled GEMM form, half-size staging for occupancy.
//   GEMM1: init = [feat | embed[idx]] @ transform   (two 32-k passes)
//   GEMM2: init @ [Ax | Ay | W0..W3 | Wself]        (128x32 @ 32x224)
// ---------------------------------------------------------------------------
__global__ __launch_bounds__(256)
void k1_init(const float* __restrict__ feat,
             const float* __restrict__ embed,
             const float* __restrict__ transform,
             const float* __restrict__ A_w,     // [96][32]; rows 0..63 = Ax,Ay
             const float* __restrict__ weight,  // [4][32][32]
             const float* __restrict__ wself,
             const int* __restrict__ idx,
             float* __restrict__ out, int n) {
    extern __shared__ float sm[];
    float* sT = sm;              // [64][32]
    float* sW = sm + 2048;       // [32][224]
    float* sF = sm + 9216;       // [32][128] (pass A: feat, pass B: embed, then sI)
    float* sI = sF;

    int tid = threadIdx.x;
    // --- stage weights (vectorized) ---
    {
        const float4* Tv = (const float4*)transform;
        for (int i = tid; i < 512; i += 256) ((float4*)sT)[i] = __ldg(Tv + i);
        const float4* Av = (const float4*)A_w;
        for (int i = tid; i < 512; i += 256) {          // Ax,Ay (rows 0..63)
            int k = (i >> 3) & 31, part = i >> 8, c4 = i & 7;
            *(float4*)&sW[k * 224 + part * 32 + c4 * 4] = __ldg(Av + i);
        }
        const float4* Wv = (const float4*)weight;
        for (int i = tid; i < 1024; i += 256) {         // W0..W3
            int b = i >> 8, k = (i >> 3) & 31, c4 = i & 7;
            *(float4*)&sW[k * 224 + 64 + b * 32 + c4 * 4] = __ldg(Wv + i);
        }
        const float4* Sv = (const float4*)wself;
        for (int i = tid; i < 256; i += 256) {          // Wself
            int k = i >> 3, c4 = i & 7;
            *(float4*)&sW[k * 224 + 192 + c4 * 4] = __ldg(Sv + i);
        }
    }

    int base = blockIdx.x * NT;
    int pS  = tid >> 7;          // staging: which half of 32 floats
    int nlS = tid & 127;
    int nodeS = base + nlS;
    int ncS = nodeS < n ? nodeS : n - 1;
    int embRow = __ldg(idx + ncS);

    // --- stage pass A: feat rows (k = 0..31) ---
    {
        const float4* fr = (const float4*)feat + (size_t)ncS * 8 + pS * 4;
#pragma unroll
        for (int q = 0; q < 4; q++) {
            float4 v = __ldg(fr + q);
            int r = pS * 16 + q * 4;
            sF[(r + 0) * NT + nlS] = v.x; sF[(r + 1) * NT + nlS] = v.y;
            sF[(r + 2) * NT + nlS] = v.z; sF[(r + 3) * NT + nlS] = v.w;
        }
    }
    __syncthreads();

    int w    = tid >> 5;
    int lane = tid & 31;
    int cg  = lane & 7;
    int ngl = lane >> 3;
    int n0  = w * 16 + ngl * 4;     // 4 nodes
    int c0  = cg * 4;               // 4 cols

    float acc[4][4];
#pragma unroll
    for (int i = 0; i < 4; i++)
#pragma unroll
        for (int j = 0; j < 4; j++) acc[i][j] = 0.f;

    // --- GEMM1 pass A (k = 0..31, feat @ transform rows 0..31) ---
#pragma unroll 8
    for (int k = 0; k < 32; k++) {
        float4 tv = *(const float4*)&sT[k * 32 + c0];
        float4 fv = *(const float4*)&sF[k * NT + n0];
        float f[4] = {fv.x, fv.y, fv.z, fv.w};
        float t[4] = {tv.x, tv.y, tv.z, tv.w};
#pragma unroll
        for (int i = 0; i < 4; i++)
#pragma unroll
            for (int j = 0; j < 4; j++)
                acc[i][j] = fmaf(f[i], t[j], acc[i][j]);
    }
    __syncthreads();

    // --- stage pass B: embed rows (k = 32..63) ---
    {
        const float4* er = (const float4*)embed + (size_t)embRow * 8 + pS * 4;
#pragma unroll
        for (int q = 0; q < 4; q++) {
            float4 v = __ldg(er + q);
            int r = pS * 16 + q * 4;
            sF[(r + 0) * NT + nlS] = v.x; sF[(r + 1) * NT + nlS] = v.y;
            sF[(r + 2) * NT + nlS] = v.z; sF[(r + 3) * NT + nlS] = v.w;
        }
    }
    __syncthreads();

    // --- GEMM1 pass B (transform rows 32..63) ---
#pragma unroll 8
    for (int k = 0; k < 32; k++) {
        float4 tv = *(const float4*)&sT[(32 + k) * 32 + c0];
        float4 fv = *(const float4*)&sF[k * NT + n0];
        float f[4] = {fv.x, fv.y, fv.z, fv.w};
        float t[4] = {tv.x, tv.y, tv.z, tv.w};
#pragma unroll
        for (int i = 0; i < 4; i++)
#pragma unroll
            for (int j = 0; j < 4; j++)
                acc[i][j] = fmaf(f[i], t[j], acc[i][j]);
    }
    __syncthreads();   // all sF reads done; sI may overwrite

    // epilogue: write init_fea to out[:,0,:] and transposed copy into sI
#pragma unroll
    for (int i = 0; i < 4; i++) {
        int node = base + n0 + i;
        if (node < n) {
            float4 v = make_float4(acc[i][0], acc[i][1], acc[i][2], acc[i][3]);
            *(float4*)&out[(size_t)node * 64 + c0] = v;
        }
#pragma unroll
        for (int j = 0; j < 4; j++)
            sI[(c0 + j) * NT + n0 + i] = acc[i][j];
    }
    __syncthreads();

    // --- GEMM2: 7 projections ---
#pragma unroll
    for (int pj = 0; pj < 7; pj++) {
        float a2[4][4];
#pragma unroll
        for (int i = 0; i < 4; i++)
#pragma unroll
            for (int j = 0; j < 4; j++) a2[i][j] = 0.f;
#pragma unroll 4
        for (int k = 0; k < 32; k++) {
            float4 nv = *(const float4*)&sI[k * NT + n0];
            float4 wv = *(const float4*)&sW[k * 224 + pj * 32 + c0];
            float f[4] = {nv.x, nv.y, nv.z, nv.w};
            float t[4] = {wv.x, wv.y, wv.z, wv.w};
#pragma unroll
            for (int i = 0; i < 4; i++)
#pragma unroll
                for (int j = 0; j < 4; j++)
                    a2[i][j] = fmaf(f[i], t[j], a2[i][j]);
        }
#pragma unroll
        for (int i = 0; i < 4; i++) {
            int node = base + n0 + i;
            if (node >= n) continue;
            float4 v = make_float4(a2[i][0], a2[i][1], a2[i][2], a2[i][3]);
            if (pj == 0) {
                *(float4*)&gPx[(size_t)node * D + c0] = v;
            } else if (pj == 1) {
                *(float4*)&gPy[(size_t)node * D + c0] = v;
            } else if (pj == 6) {
                *(float4*)&gAgg[(size_t)node * D + c0] = v;
            } else {
                int b = pj - 2;
                __half2 h01 = __floats2half2_rn(v.x, v.y);
                __half2 h23 = __floats2half2_rn(v.z, v.w);
                uint2 pk;
                pk.x = *(unsigned*)&h01;
                pk.y = *(unsigned*)&h23;
                *(uint2*)&gSh[(size_t)node * 128 + cg * 16 + b * 4] = pk;
            }
        }
    }
}

// ---------------------------------------------------------------------------
// K2: edge kernel. 4 edges/warp, 8 lanes/edge (lane c = float4 chunk).
// ---------------------------------------------------------------------------
__global__ __launch_bounds__(256)
void k2_edges(const float* __restrict__ A_w, const float* __restrict__ A_b,
              const float* __restrict__ B_w, const float* __restrict__ B_b,
              const float* __restrict__ attn, const float* __restrict__ wcomp,
              const int* __restrict__ esrc, const int* __restrict__ edst,
              const int* __restrict__ etyp, int nE) {
    __shared__ float sPr[NREL * D];
    __shared__ float sWc[NREL * NBASE];
    int tid = threadIdx.x;
    for (int i = tid; i < NREL * D; i += 256) {
        int t = i >> 5, o = i & 31;
        float acc = __ldg(A_b + o);
#pragma unroll
        for (int k = 0; k < D; k++)
            acc = fmaf(__ldg(attn + t * D + k), __ldg(A_w + (64 + k) * D + o), acc);
        sPr[i] = acc;
    }
    if (tid < NREL * NBASE) sWc[tid] = wcomp[tid];
    __syncthreads();

    int lane = tid & 31;
    int c    = lane & 7;
    int ei   = lane >> 3;
    float Bb = __ldg(B_b);
    float4 Bw4 = __ldg((const float4*)B_w + c);

    int gwarp = (blockIdx.x * blockDim.x + tid) >> 5;
    int nWarps = (gridDim.x * blockDim.x) >> 5;
    int nQ = (nE + 3) >> 2;

    const float4* Pxv = (const float4*)gPx;
    const float4* Pyv = (const float4*)gPy;
    const uint4*  Zv  = (const uint4*)gSh;
    const float4* Prv = (const float4*)sPr;
    const float4* Wcv = (const float4*)sWc;

    for (int q = gwarp; q < nQ; q += nWarps) {
        int ge = q * 4 + ei;
        bool valid = ge < nE;
        int gc = valid ? ge : (nE - 1);
        int src = __ldg(esrc + gc);
        int dst = __ldg(edst + gc);
        int typ = __ldg(etyp + gc);

        float4 px4 = __ldg(Pxv + (size_t)src * 8 + c);
        float4 py4 = __ldg(Pyv + (size_t)dst * 8 + c);
        uint4 u0 = __ldg(Zv + (size_t)src * 16 + c * 2);       // b0,b1
        uint4 u1 = __ldg(Zv + (size_t)src * 16 + c * 2 + 1);   // b2,b3
        float4 pr4 = Prv[typ * 8 + c];

        float hx = fmaxf(px4.x + py4.x + pr4.x, 0.f);
        float hy = fmaxf(px4.y + py4.y + pr4.y, 0.f);
        float hz = fmaxf(px4.z + py4.z + pr4.z, 0.f);
        float hw = fmaxf(px4.w + py4.w + pr4.w, 0.f);
        float s = hx * Bw4.x + hy * Bw4.y + hz * Bw4.z + hw * Bw4.w;
        s += __shfl_xor_sync(0xffffffffu, s, 1);
        s += __shfl_xor_sync(0xffffffffu, s, 2);
        s += __shfl_xor_sync(0xffffffffu, s, 4);
        float a = 1.f / (1.f + __expf(-(s + Bb)));

        float2 f00 = __half22float2(*(const __half2*)&u0.x);
        float2 f01 = __half22float2(*(const __half2*)&u0.y);
        float2 f10 = __half22float2(*(const __half2*)&u0.z);
        float2 f11 = __half22float2(*(const __half2*)&u0.w);
        float2 f20 = __half22float2(*(const __half2*)&u1.x);
        float2 f21 = __half22float2(*(const __half2*)&u1.y);
        float2 f30 = __half22float2(*(const __half2*)&u1.z);
        float2 f31 = __half22float2(*(const __half2*)&u1.w);

        float4 wc = Wcv[typ];
        float mx = wc.x * f00.x; mx = fmaf(wc.y, f10.x, mx); mx = fmaf(wc.z, f20.x, mx); mx = fmaf(wc.w, f30.x, mx);
        float my = wc.x * f00.y; my = fmaf(wc.y, f10.y, my); my = fmaf(wc.z, f20.y, my); my = fmaf(wc.w, f30.y, my);
        float mz = wc.x * f01.x; mz = fmaf(wc.y, f11.x, mz); mz = fmaf(wc.z, f21.x, mz); mz = fmaf(wc.w, f31.x, mz);
        float mw = wc.x * f01.y; mw = fmaf(wc.y, f11.y, mw); mw = fmaf(wc.z, f21.y, mw); mw = fmaf(wc.w, f31.y, mw);
        mx *= a; my *= a; mz *= a; mw *= a;

        if (valid) {
            float* p = &gAgg[(size_t)dst * D + c * 4];
            asm volatile("red.global.add.v4.f32 [%0], {%1,%2,%3,%4};"
                         :: "l"(p), "f"(mx), "f"(my), "f"(mz), "f"(mw)
                         : "memory");
        }
    }
}

// ---------------------------------------------------------------------------
// K3: repr[:,1,:] = relu(gAgg)
// ---------------------------------------------------------------------------
__global__ void k3_final(float* __restrict__ out, int n) {
    int i = blockIdx.x * blockDim.x + threadIdx.x;
    int total = n * 8;
    if (i >= total) return;
    int v = i >> 3, cc = i & 7;
    float4 g = ((const float4*)gAgg)[i];
    float4 r;
    r.x = fmaxf(g.x, 0.f); r.y = fmaxf(g.y, 0.f);
    r.z = fmaxf(g.z, 0.f); r.w = fmaxf(g.w, 0.f);
    ((float4*)out)[(size_t)v * 16 + 8 + cc] = r;
}

// ---------------------------------------------------------------------------
extern "C" void kernel_launch(void* const* d_in, const int* in_sizes, int n_in,
                              void* d_out, int out_size) {
    const float* feat      = (const float*)d_in[0];
    const float* embed     = (const float*)d_in[1];
    const float* transform = (const float*)d_in[2];
    const float* weight    = (const float*)d_in[3];
    const float* wcomp     = (const float*)d_in[4];
    const float* wself     = (const float*)d_in[5];
    const float* A_w       = (const float*)d_in[6];
    const float* A_b       = (const float*)d_in[7];
    const float* B_w       = (const float*)d_in[8];
    const float* B_b       = (const float*)d_in[9];
    const float* attn      = (const float*)d_in[10];
    const int*   idx       = (const int*)d_in[11];
    const int*   esrc      = (const int*)d_in[12];
    const int*   edst      = (const int*)d_in[13];
    const int*   etyp      = (const int*)d_in[14];

    int n  = in_sizes[0] / D;       // 50000
    int nE = in_sizes[12];          // 800000
    float* out = (float*)d_out;

    cudaFuncSetAttribute(k1_init, cudaFuncAttributeMaxDynamicSharedMemorySize, K1_SMEM_BYTES);

    k1_init<<<(n + NT - 1) / NT, 256, K1_SMEM_BYTES>>>(feat, embed, transform, A_w,
                                                       weight, wself, idx, out, n);
    k2_edges<<<1184, 256>>>(A_w, A_b, B_w, B_b, attn, wcomp, esrc, edst, etyp, nE);
    k3_final<<<(n * 8 + 255) / 256, 256>>>(out, n);
}

// round 6
// speedup vs baseline: 4.6078x; 1.0277x over previous
#include <cuda_runtime.h>
#include <cuda_fp16.h>

#define D        32
#define NREL     16
#define NBASE    4
#define MAX_NODES 50176
#define NT       128          // nodes per k1 block

// Per-node src record: 160 halfs = 320 B : px[32] | z[128] (z chunk c: b0..b3 x4)
__device__ __half gSrc[MAX_NODES * 160];
__device__ __half gPyh[MAX_NODES * 32];
__device__ float  gAgg[MAX_NODES * D];          // init: curr = init_fea @ Wself

// k1 SMEM: sT[64*32]=2048 | sW[32*224]=7168 | sF[32*128]=4096 (two passes; sI aliases)
#define K1_SMEM_FLOATS (2048 + 7168 + 4096)
#define K1_SMEM_BYTES  (K1_SMEM_FLOATS * 4)

// ---------------------------------------------------------------------------
// K1: per-node precompute, tiled GEMM form.
//   GEMM1: init = [feat | embed[idx]] @ transform   (two 32-k passes)
//   GEMM2: init @ [Ax | Ay | W0..W3 | Wself]        (128x32 @ 32x224)
// ---------------------------------------------------------------------------
__global__ __launch_bounds__(256)
void k1_init(const float* __restrict__ feat,
             const float* __restrict__ embed,
             const float* __restrict__ transform,
             const float* __restrict__ A_w,     // [96][32]; rows 0..63 = Ax,Ay
             const float* __restrict__ weight,  // [4][32][32]
             const float* __restrict__ wself,
             const int* __restrict__ idx,
             float* __restrict__ out, int n) {
    extern __shared__ float sm[];
    float* sT = sm;              // [64][32]
    float* sW = sm + 2048;       // [32][224]
    float* sF = sm + 9216;       // [32][128]
    float* sI = sF;

    int tid = threadIdx.x;
    {
        const float4* Tv = (const float4*)transform;
        for (int i = tid; i < 512; i += 256) ((float4*)sT)[i] = __ldg(Tv + i);
        const float4* Av = (const float4*)A_w;
        for (int i = tid; i < 512; i += 256) {          // Ax,Ay (rows 0..63)
            int k = (i >> 3) & 31, part = i >> 8, c4 = i & 7;
            *(float4*)&sW[k * 224 + part * 32 + c4 * 4] = __ldg(Av + i);
        }
        const float4* Wv = (const float4*)weight;
        for (int i = tid; i < 1024; i += 256) {         // W0..W3
            int b = i >> 8, k = (i >> 3) & 31, c4 = i & 7;
            *(float4*)&sW[k * 224 + 64 + b * 32 + c4 * 4] = __ldg(Wv + i);
        }
        const float4* Sv = (const float4*)wself;
        for (int i = tid; i < 256; i += 256) {          // Wself
            int k = i >> 3, c4 = i & 7;
            *(float4*)&sW[k * 224 + 192 + c4 * 4] = __ldg(Sv + i);
        }
    }

    int base = blockIdx.x * NT;
    int pS  = tid >> 7;
    int nlS = tid & 127;
    int nodeS = base + nlS;
    int ncS = nodeS < n ? nodeS : n - 1;
    int embRow = __ldg(idx + ncS);

    // --- stage pass A: feat rows ---
    {
        const float4* fr = (const float4*)feat + (size_t)ncS * 8 + pS * 4;
#pragma unroll
        for (int q = 0; q < 4; q++) {
            float4 v = __ldg(fr + q);
            int r = pS * 16 + q * 4;
            sF[(r + 0) * NT + nlS] = v.x; sF[(r + 1) * NT + nlS] = v.y;
            sF[(r + 2) * NT + nlS] = v.z; sF[(r + 3) * NT + nlS] = v.w;
        }
    }
    __syncthreads();

    int w    = tid >> 5;
    int lane = tid & 31;
    int cg  = lane & 7;
    int ngl = lane >> 3;
    int n0  = w * 16 + ngl * 4;
    int c0  = cg * 4;

    float acc[4][4];
#pragma unroll
    for (int i = 0; i < 4; i++)
#pragma unroll
        for (int j = 0; j < 4; j++) acc[i][j] = 0.f;

#pragma unroll 8
    for (int k = 0; k < 32; k++) {
        float4 tv = *(const float4*)&sT[k * 32 + c0];
        float4 fv = *(const float4*)&sF[k * NT + n0];
        float f[4] = {fv.x, fv.y, fv.z, fv.w};
        float t[4] = {tv.x, tv.y, tv.z, tv.w};
#pragma unroll
        for (int i = 0; i < 4; i++)
#pragma unroll
            for (int j = 0; j < 4; j++)
                acc[i][j] = fmaf(f[i], t[j], acc[i][j]);
    }
    __syncthreads();

    // --- stage pass B: embed rows ---
    {
        const float4* er = (const float4*)embed + (size_t)embRow * 8 + pS * 4;
#pragma unroll
        for (int q = 0; q < 4; q++) {
            float4 v = __ldg(er + q);
            int r = pS * 16 + q * 4;
            sF[(r + 0) * NT + nlS] = v.x; sF[(r + 1) * NT + nlS] = v.y;
            sF[(r + 2) * NT + nlS] = v.z; sF[(r + 3) * NT + nlS] = v.w;
        }
    }
    __syncthreads();

#pragma unroll 8
    for (int k = 0; k < 32; k++) {
        float4 tv = *(const float4*)&sT[(32 + k) * 32 + c0];
        float4 fv = *(const float4*)&sF[k * NT + n0];
        float f[4] = {fv.x, fv.y, fv.z, fv.w};
        float t[4] = {tv.x, tv.y, tv.z, tv.w};
#pragma unroll
        for (int i = 0; i < 4; i++)
#pragma unroll
            for (int j = 0; j < 4; j++)
                acc[i][j] = fmaf(f[i], t[j], acc[i][j]);
    }
    __syncthreads();

    // epilogue: write init_fea to out[:,0,:] and transposed copy into sI
#pragma unroll
    for (int i = 0; i < 4; i++) {
        int node = base + n0 + i;
        if (node < n) {
            float4 v = make_float4(acc[i][0], acc[i][1], acc[i][2], acc[i][3]);
            *(float4*)&out[(size_t)node * 64 + c0] = v;
        }
#pragma unroll
        for (int j = 0; j < 4; j++)
            sI[(c0 + j) * NT + n0 + i] = acc[i][j];
    }
    __syncthreads();

    // --- GEMM2: 7 projections ---
#pragma unroll
    for (int pj = 0; pj < 7; pj++) {
        float a2[4][4];
#pragma unroll
        for (int i = 0; i < 4; i++)
#pragma unroll
            for (int j = 0; j < 4; j++) a2[i][j] = 0.f;
#pragma unroll 4
        for (int k = 0; k < 32; k++) {
            float4 nv = *(const float4*)&sI[k * NT + n0];
            float4 wv = *(const float4*)&sW[k * 224 + pj * 32 + c0];
            float f[4] = {nv.x, nv.y, nv.z, nv.w};
            float t[4] = {wv.x, wv.y, wv.z, wv.w};
#pragma unroll
            for (int i = 0; i < 4; i++)
#pragma unroll
                for (int j = 0; j < 4; j++)
                    a2[i][j] = fmaf(f[i], t[j], a2[i][j]);
        }
#pragma unroll
        for (int i = 0; i < 4; i++) {
            int node = base + n0 + i;
            if (node >= n) continue;
            float4 v = make_float4(a2[i][0], a2[i][1], a2[i][2], a2[i][3]);
            __half2 h01 = __floats2half2_rn(v.x, v.y);
            __half2 h23 = __floats2half2_rn(v.z, v.w);
            uint2 pk;
            pk.x = *(unsigned*)&h01;
            pk.y = *(unsigned*)&h23;
            if (pj == 0) {            // px fp16 -> gSrc[0..32)
                *(uint2*)&gSrc[(size_t)node * 160 + cg * 4] = pk;
            } else if (pj == 1) {     // py fp16
                *(uint2*)&gPyh[(size_t)node * 32 + cg * 4] = pk;
            } else if (pj == 6) {     // curr fp32
                *(float4*)&gAgg[(size_t)node * D + c0] = v;
            } else {                  // z_b fp16 -> gSrc[32 + c*16 + b*4]
                int b = pj - 2;
                *(uint2*)&gSrc[(size_t)node * 160 + 32 + cg * 16 + b * 4] = pk;
            }
        }
    }
}

// ---------------------------------------------------------------------------
// K2: edge kernel. 4 edges/warp, 8 lanes/edge (lane c = float4 chunk).
// ---------------------------------------------------------------------------
__global__ __launch_bounds__(256)
void k2_edges(const float* __restrict__ A_w, const float* __restrict__ A_b,
              const float* __restrict__ B_w, const float* __restrict__ B_b,
              const float* __restrict__ attn, const float* __restrict__ wcomp,
              const int* __restrict__ esrc, const int* __restrict__ edst,
              const int* __restrict__ etyp, int nE) {
    __shared__ float sPr[NREL * D];
    __shared__ float sWc[NREL * NBASE];
    int tid = threadIdx.x;
    for (int i = tid; i < NREL * D; i += 256) {
        int t = i >> 5, o = i & 31;
        float acc = __ldg(A_b + o);
#pragma unroll
        for (int k = 0; k < D; k++)
            acc = fmaf(__ldg(attn + t * D + k), __ldg(A_w + (64 + k) * D + o), acc);
        sPr[i] = acc;
    }
    if (tid < NREL * NBASE) sWc[tid] = wcomp[tid];
    __syncthreads();

    int lane = tid & 31;
    int c    = lane & 7;
    int ei   = lane >> 3;
    float Bb = __ldg(B_b);
    float4 Bw4 = __ldg((const float4*)B_w + c);

    int gwarp = (blockIdx.x * blockDim.x + tid) >> 5;
    int nWarps = (gridDim.x * blockDim.x) >> 5;
    int nQ = (nE + 3) >> 2;

    const uint2* Pxv = (const uint2*)gSrc;   // 40 uint2 per node
    const uint4* Zv  = (const uint4*)gSrc;   // 20 uint4 per node; z at +4
    const uint2* Pyv = (const uint2*)gPyh;   // 8 uint2 per node
    const float4* Prv = (const float4*)sPr;
    const float4* Wcv = (const float4*)sWc;

    for (int q = gwarp; q < nQ; q += nWarps) {
        int ge = q * 4 + ei;
        bool valid = ge < nE;
        int gc = valid ? ge : (nE - 1);
        int src = __ldg(esrc + gc);
        int dst = __ldg(edst + gc);
        int typ = __ldg(etyp + gc);

        uint2 pxu = __ldg(Pxv + (size_t)src * 40 + c);
        uint2 pyu = __ldg(Pyv + (size_t)dst * 8 + c);
        uint4 u0  = __ldg(Zv + (size_t)src * 20 + 4 + c * 2);      // b0,b1
        uint4 u1  = __ldg(Zv + (size_t)src * 20 + 5 + c * 2);      // b2,b3
        float4 pr4 = Prv[typ * 8 + c];

        float2 px01 = __half22float2(*(const __half2*)&pxu.x);
        float2 px23 = __half22float2(*(const __half2*)&pxu.y);
        float2 py01 = __half22float2(*(const __half2*)&pyu.x);
        float2 py23 = __half22float2(*(const __half2*)&pyu.y);

        float hx = fmaxf(px01.x + py01.x + pr4.x, 0.f);
        float hy = fmaxf(px01.y + py01.y + pr4.y, 0.f);
        float hz = fmaxf(px23.x + py23.x + pr4.z, 0.f);
        float hw = fmaxf(px23.y + py23.y + pr4.w, 0.f);
        float s = hx * Bw4.x + hy * Bw4.y + hz * Bw4.z + hw * Bw4.w;
        s += __shfl_xor_sync(0xffffffffu, s, 1);
        s += __shfl_xor_sync(0xffffffffu, s, 2);
        s += __shfl_xor_sync(0xffffffffu, s, 4);
        float a = 1.f / (1.f + __expf(-(s + Bb)));

        float2 f00 = __half22float2(*(const __half2*)&u0.x);
        float2 f01 = __half22float2(*(const __half2*)&u0.y);
        float2 f10 = __half22float2(*(const __half2*)&u0.z);
        float2 f11 = __half22float2(*(const __half2*)&u0.w);
        float2 f20 = __half22float2(*(const __half2*)&u1.x);
        float2 f21 = __half22float2(*(const __half2*)&u1.y);
        float2 f30 = __half22float2(*(const __half2*)&u1.z);
        float2 f31 = __half22float2(*(const __half2*)&u1.w);

        float4 wc = Wcv[typ];
        float mx = wc.x * f00.x; mx = fmaf(wc.y, f10.x, mx); mx = fmaf(wc.z, f20.x, mx); mx = fmaf(wc.w, f30.x, mx);
        float my = wc.x * f00.y; my = fmaf(wc.y, f10.y, my); my = fmaf(wc.z, f20.y, my); my = fmaf(wc.w, f30.y, my);
        float mz = wc.x * f01.x; mz = fmaf(wc.y, f11.x, mz); mz = fmaf(wc.z, f21.x, mz); mz = fmaf(wc.w, f31.x, mz);
        float mw = wc.x * f01.y; mw = fmaf(wc.y, f11.y, mw); mw = fmaf(wc.z, f21.y, mw); mw = fmaf(wc.w, f31.y, mw);
        mx *= a; my *= a; mz *= a; mw *= a;

        if (valid) {
            float* p = &gAgg[(size_t)dst * D + c * 4];
            asm volatile("red.global.add.v4.f32 [%0], {%1,%2,%3,%4};"
                         :: "l"(p), "f"(mx), "f"(my), "f"(mz), "f"(mw)
                         : "memory");
        }
    }
}

// ---------------------------------------------------------------------------
// K3: repr[:,1,:] = relu(gAgg), 4 float4 per thread
// ---------------------------------------------------------------------------
__global__ void k3_final(float* __restrict__ out, int n) {
    int total = n * 8;
    int stride = gridDim.x * blockDim.x;
    int i0 = blockIdx.x * blockDim.x + threadIdx.x;
#pragma unroll 4
    for (int it = 0; it < 4; it++) {
        int i = i0 + it * stride;
        if (i < total) {
            int v = i >> 3, cc = i & 7;
            float4 g = ((const float4*)gAgg)[i];
            float4 r;
            r.x = fmaxf(g.x, 0.f); r.y = fmaxf(g.y, 0.f);
            r.z = fmaxf(g.z, 0.f); r.w = fmaxf(g.w, 0.f);
            ((float4*)out)[(size_t)v * 16 + 8 + cc] = r;
        }
    }
}

// ---------------------------------------------------------------------------
extern "C" void kernel_launch(void* const* d_in, const int* in_sizes, int n_in,
                              void* d_out, int out_size) {
    const float* feat      = (const float*)d_in[0];
    const float* embed     = (const float*)d_in[1];
    const float* transform = (const float*)d_in[2];
    const float* weight    = (const float*)d_in[3];
    const float* wcomp     = (const float*)d_in[4];
    const float* wself     = (const float*)d_in[5];
    const float* A_w       = (const float*)d_in[6];
    const float* A_b       = (const float*)d_in[7];
    const float* B_w       = (const float*)d_in[8];
    const float* B_b       = (const float*)d_in[9];
    const float* attn      = (const float*)d_in[10];
    const int*   idx       = (const int*)d_in[11];
    const int*   esrc      = (const int*)d_in[12];
    const int*   edst      = (const int*)d_in[13];
    const int*   etyp      = (const int*)d_in[14];

    int n  = in_sizes[0] / D;       // 50000
    int nE = in_sizes[12];          // 800000
    float* out = (float*)d_out;

    cudaFuncSetAttribute(k1_init, cudaFuncAttributeMaxDynamicSharedMemorySize, K1_SMEM_BYTES);

    k1_init<<<(n + NT - 1) / NT, 256, K1_SMEM_BYTES>>>(feat, embed, transform, A_w,
                                                       weight, wself, idx, out, n);
    k2_edges<<<1184, 256>>>(A_w, A_b, B_w, B_b, attn, wcomp, esrc, edst, etyp, nE);
    k3_final<<<(n * 8 + 4 * 256 - 1) / (4 * 256), 256>>>(out, n);
}